// round 3
// baseline (speedup 1.0000x reference)
#include <cuda_runtime.h>
#include <cuda_bf16.h>

#define HN 4096
#define HROWS 8192
#define WST 17                  // chunk stride: 16-float chunk at [17l, 17l+16)
#define WK_FLOATS 4352          // 255*17 + 16 = 4351, padded
#define PST 273                 // s_perm chunk stride (273 mod 32 = 17, injective: >=256)
#define SP_FLOATS 4352          // 15*273 + 255 = 4350, padded

// fwdp[k] = pre-encoded s_perm address of column j where P[k,j]=1:
//   enc(j) = (j&15)*PST + ((j>>4)&15)*16 + (j>>8)
__device__ __align__(16) int d_fwdp[HN];

__device__ __forceinline__ int perm_enc(int j) {
    return (j & 15) * PST + ((j >> 4) & 15) * 16 + (j >> 8);
}

// ---------------------------------------------------------------------------
// Kernel 1: extract permutation from one-hot P [N,N]; 8 float4/thread (MLP=8).
// ---------------------------------------------------------------------------
__global__ void __launch_bounds__(256)
extract_perm_kernel(const float* __restrict__ P) {
    int base = blockIdx.x * 2048 + threadIdx.x;   // float4 index
#pragma unroll
    for (int q = 0; q < 8; q++) {
        int f4i = base + q * 256;
        float4 v = __ldcs(reinterpret_cast<const float4*>(P) + f4i);
        int e = f4i << 2;          // element index
        int k = e >> 12;           // row of P
        int j = e & (HN - 1);      // starting column
        if (v.x != 0.0f) d_fwdp[k] = perm_enc(j + 0);
        if (v.y != 0.0f) d_fwdp[k] = perm_enc(j + 1);
        if (v.z != 0.0f) d_fwdp[k] = perm_enc(j + 2);
        if (v.w != 0.0f) d_fwdp[k] = perm_enc(j + 3);
    }
}

// ---------------------------------------------------------------------------
// Kernel 2: per-row FWHT (x 1/64) + permutation add, fused. 1 row/block.
// i = a*256 + b*16 + c.
//   state A: addr = (a*16+b)*17 + c   (pass1 store CF, pass2 read CF)
//   state B: addr = (b*16+c)*17 + a   (pass2 write ~CF, pass3 read ~CF)
//   s_perm : addr = c*273 + b*16 + a  (epilogue read CF; scatter random)
// ---------------------------------------------------------------------------
__device__ __forceinline__ void fwht16(float v[16]) {
#pragma unroll
    for (int h = 8; h >= 1; h >>= 1) {
#pragma unroll
        for (int g = 0; g < 16; g += 2 * h) {
#pragma unroll
            for (int l = 0; l < h; l++) {
                float x = v[g + l];
                float y = v[g + l + h];
                v[g + l]     = x + y;
                v[g + l + h] = x - y;
            }
        }
    }
}

__global__ void __launch_bounds__(256, 6)
fwht_kernel(const float* __restrict__ value, float* __restrict__ out) {
    __shared__ float wk[WK_FLOATS];
    __shared__ float sp[SP_FLOATS];

    const int t = threadIdx.x;
    const size_t row = (size_t)blockIdx.x;

    float v[16];

    // ---- load row (coalesced float4) + scatter original into permuted layout,
    // interleaved quarter-by-quarter to keep register pressure low.
    {
        const float4* in4 = reinterpret_cast<const float4*>(value + row * HN) + t * 4;
        const int4*   fp  = reinterpret_cast<const int4*>(d_fwdp) + t * 4;
#pragma unroll
        for (int q = 0; q < 4; q++) {
            float4 x = __ldcs(in4 + q);
            int4   w = __ldg(fp + q);
            sp[w.x] = x.x; sp[w.y] = x.y; sp[w.z] = x.z; sp[w.w] = x.w;
            v[q * 4 + 0] = x.x; v[q * 4 + 1] = x.y;
            v[q * 4 + 2] = x.z; v[q * 4 + 3] = x.w;
        }
    }

    // ---- pass 1 (c): fwht on contiguous 16, store state A
    fwht16(v);
#pragma unroll
    for (int c = 0; c < 16; c++) wk[t * WST + c] = v[c];
    __syncthreads();

    // ---- pass 2 (b): read state A, fwht, write state B (same buffer)
    {
        const int a = t >> 4, c = t & 15;
        float u[16];
#pragma unroll
        for (int b = 0; b < 16; b++) u[b] = wk[(a * 16 + b) * WST + c];
        __syncthreads();              // all reads of A before writes of B
        fwht16(u);
#pragma unroll
        for (int b = 0; b < 16; b++) wk[(b * 16 + c) * WST + a] = u[b];
    }
    __syncthreads();

    // ---- pass 3 (a) + epilogue: read state B, fwht, add permuted orig, store
    {
        const int b = t >> 4, c = t & 15;
        float u[16];
#pragma unroll
        for (int a = 0; a < 16; a++) u[a] = wk[(b * 16 + c) * WST + a];
        fwht16(u);
        const float* spp  = sp + c * PST + b * 16;
        float*       orow = out + row * HN + b * 16 + c;
#pragma unroll
        for (int a = 0; a < 16; a++) {
            // lanes (2 b-values x 16 c) -> 32 consecutive floats: coalesced 128B
            __stcs(orow + a * 256, u[a] * 0.015625f + spp[a]);
        }
    }
}

// ---------------------------------------------------------------------------
// Inputs (metadata order): value [ROWS*N], weight [N*N] (exact H/64, unused),
// permutation [N*N].
// ---------------------------------------------------------------------------
extern "C" void kernel_launch(void* const* d_in, const int* in_sizes, int n_in,
                              void* d_out, int out_size) {
    const float* value = (const float*)d_in[0];
    const float* P     = (const float*)d_in[2];
    float* out         = (float*)d_out;
    (void)in_sizes; (void)n_in; (void)out_size;

    // 4096*4096/4 float4 / 2048 per block = 2048 blocks
    extract_perm_kernel<<<(HN * HN) / 4 / 2048, 256>>>(P);
    fwht_kernel<<<HROWS, 256>>>(value, out);
}

// round 5
// speedup vs baseline: 1.1102x; 1.1102x over previous
#include <cuda_runtime.h>
#include <cuda_bf16.h>

#define HN 4096
#define HROWS 8192
#define WST 17                  // chunk stride: 16-float chunk at [17l, 17l+16)
#define WK_FLOATS 4352
#define NEXTRACT 128            // blocks doing permutation extraction (wave-1 resident)

// d_invp[j] = padded smem address of inv[j]: pad17(k) where P[k,j]==1.
__device__ __align__(16) int d_invp[HN];
__device__ int d_done = 0;      // extraction completion counter (monotonic across replays)

__device__ __forceinline__ int pad17(int i) { return (i >> 4) * WST + (i & 15); }

__device__ __forceinline__ void fwht16(float v[16]) {
#pragma unroll
    for (int h = 8; h >= 1; h >>= 1) {
#pragma unroll
        for (int g = 0; g < 16; g += 2 * h) {
#pragma unroll
            for (int l = 0; l < h; l++) {
                float x = v[g + l];
                float y = v[g + l + h];
                v[g + l]     = x + y;
                v[g + l + h] = x - y;
            }
        }
    }
}

// ---------------------------------------------------------------------------
// Fused kernel. Block b processes row b. Blocks < NEXTRACT first extract their
// slice of the one-hot P, then signal d_done (release). All blocks: load row
// -> store orig CF in sp -> FWHT passes 1..3 (stride-17 CF layouts) -> wait
// for extraction -> gather permuted orig via L2-coherent loads -> store.
// ---------------------------------------------------------------------------
__global__ void __launch_bounds__(256, 6)
fused_fwht_kernel(const float* __restrict__ value,
                  const float* __restrict__ P,
                  float* __restrict__ out) {
    __shared__ float wk[WK_FLOATS];   // FWHT work buffer
    __shared__ float sp[WK_FLOATS];   // original row, natural order, padded

    const int t   = threadIdx.x;
    const int bid = blockIdx.x;

    // ================= extraction (blocks 0..127 only) =================
    if (bid < NEXTRACT) {
        // 64MB / 128 blocks = 512KB = 32768 float4; 128 float4/thread.
        const float4* p4 = reinterpret_cast<const float4*>(P)
                         + (size_t)bid * 32768 + t;
        const int ebase = bid * 32768;            // block's first float4 index
#pragma unroll 1
        for (int it = 0; it < 32; it++) {
            float4 r[4];
#pragma unroll
            for (int q = 0; q < 4; q++)
                r[q] = __ldcs(p4 + (size_t)(it * 4 + q) * 256);
#pragma unroll
            for (int q = 0; q < 4; q++) {
                if (r[q].x != 0.0f || r[q].y != 0.0f ||
                    r[q].z != 0.0f || r[q].w != 0.0f) {   // rare (one-hot)
                    int e = (ebase + (it * 4 + q) * 256 + t) << 2;
                    int k = e >> 12;           // row of P
                    int j = e & (HN - 1);      // column
                    if (r[q].x != 0.0f) d_invp[j + 0] = pad17(k);
                    if (r[q].y != 0.0f) d_invp[j + 1] = pad17(k);
                    if (r[q].z != 0.0f) d_invp[j + 2] = pad17(k);
                    if (r[q].w != 0.0f) d_invp[j + 3] = pad17(k);
                }
            }
        }
        __syncthreads();
        if (t == 0) {
            __threadfence();                   // release d_invp writes to L2
            atomicAdd(&d_done, 1);
        }
    }

    // ================= per-row FWHT =================
    const size_t row = (size_t)bid;
    float v[16];

    // load row (coalesced float4) + store original CF: bank(17t+c) distinct per c
    {
        const float4* in4 = reinterpret_cast<const float4*>(value + row * HN) + t * 4;
#pragma unroll
        for (int q = 0; q < 4; q++) {
            float4 x = __ldcs(in4 + q);
            v[q * 4 + 0] = x.x; v[q * 4 + 1] = x.y;
            v[q * 4 + 2] = x.z; v[q * 4 + 3] = x.w;
        }
#pragma unroll
        for (int c = 0; c < 16; c++) sp[t * WST + c] = v[c];
    }

    // pass 1 (c-bits): fwht contiguous 16, store state A: addr=(a*16+b)*17+c
    fwht16(v);
#pragma unroll
    for (int c = 0; c < 16; c++) wk[t * WST + c] = v[c];
    __syncthreads();

    // pass 2 (b-bits): read A (CF), fwht, write state B: addr=(b*16+c)*17+a (CF)
    {
        const int a = t >> 4, c = t & 15;
        float u[16];
#pragma unroll
        for (int b = 0; b < 16; b++) u[b] = wk[(a * 16 + b) * WST + c];
        __syncthreads();              // reads of A complete before B overwrites
        fwht16(u);
#pragma unroll
        for (int b = 0; b < 16; b++) wk[(b * 16 + c) * WST + a] = u[b];
    }
    __syncthreads();

    // pass 3 (a-bits): read B (CF), fwht
    const int b = t >> 4, c = t & 15;
    float u[16];
#pragma unroll
    for (int a = 0; a < 16; a++) u[a] = wk[(b * 16 + c) * WST + a];
    fwht16(u);

    // wait for extraction (satisfied immediately on replays; on the first run
    // it is hidden behind passes 1-3 of the early waves)
    if (t == 0) {
        while (*(volatile int*)&d_done < NEXTRACT) __nanosleep(32);
        __threadfence();              // acquire side
    }
    __syncthreads();

    // epilogue: out[j] = fwht[j]/64 + orig[inv[j]]
    // d_invp is written THIS launch -> must use L2-coherent loads (NOT __ldg).
    {
        const int jb = b * 16 + c;
        float* orow = out + row * HN + jb;
#pragma unroll
        for (int a = 0; a < 16; a++) {
            int ip = __ldcg(d_invp + a * 256 + jb);  // lanes: consecutive j -> 128B
            __stcs(orow + a * 256, u[a] * 0.015625f + sp[ip]);
        }
    }
}

// ---------------------------------------------------------------------------
// Inputs (metadata order): value [ROWS*N], weight [N*N] (exact H/64, unused),
// permutation [N*N].
// ---------------------------------------------------------------------------
extern "C" void kernel_launch(void* const* d_in, const int* in_sizes, int n_in,
                              void* d_out, int out_size) {
    const float* value = (const float*)d_in[0];
    const float* P     = (const float*)d_in[2];
    float* out         = (float*)d_out;
    (void)in_sizes; (void)n_in; (void)out_size;

    fused_fwht_kernel<<<HROWS, 256>>>(value, P, out);
}

// round 6
// speedup vs baseline: 1.1458x; 1.0321x over previous
#include <cuda_runtime.h>
#include <cuda_bf16.h>

#define HN 4096
#define HROWS 8192
#define RPB 2
#define WST 17                  // wk chunk stride (16-float chunk at [17l, 17l+16))
#define PST 273                 // sp chunk stride; epilogue banks 17c+16b+a: CF
#define WK_FLOATS 4352
#define SP_FLOATS 4352
#define NEXTRACT 128            // extractor blocks (wave-1 resident)

// d_fwdp[k] = pre-encoded sp scatter address of column j where P[k,j]==1:
//   enc(j) = (j&15)*PST + ((j>>4)&15)*16 + (j>>8)
__device__ __align__(16) int d_fwdp[HN];
__device__ int d_done = 0;      // monotonic across graph replays

__device__ __forceinline__ int perm_enc(int j) {
    return (j & 15) * PST + ((j >> 4) & 15) * 16 + (j >> 8);
}

__device__ __forceinline__ void fwht16(float v[16]) {
#pragma unroll
    for (int h = 8; h >= 1; h >>= 1) {
#pragma unroll
        for (int g = 0; g < 16; g += 2 * h) {
#pragma unroll
            for (int l = 0; l < h; l++) {
                float x = v[g + l];
                float y = v[g + l + h];
                v[g + l]     = x + y;
                v[g + l + h] = x - y;
            }
        }
    }
}

// ---------------------------------------------------------------------------
// Fused kernel, RPB=2 rows per block. Blocks < NEXTRACT first extract their
// 512KB slice of one-hot P into d_fwdp (release via fenced counter). Every
// block: issue row loads -> wait flag (instant on replays) -> load idx[16]
// into regs -> per row: scatter orig into sp (permuted layout), FWHT passes
// 1..3 in CF stride-17 layouts, epilogue = CF sp read + FFMA + coalesced STG.
// ---------------------------------------------------------------------------
__global__ void __launch_bounds__(256, 4)
fused_fwht_kernel(const float* __restrict__ value,
                  const float* __restrict__ P,
                  float* __restrict__ out) {
    __shared__ float wk[WK_FLOATS];   // FWHT work buffer
    __shared__ float sp[SP_FLOATS];   // original row in permuted layout

    const int t   = threadIdx.x;
    const int bid = blockIdx.x;

    // ================= extraction (blocks 0..127) =================
    if (bid < NEXTRACT) {
        const float4* p4 = reinterpret_cast<const float4*>(P)
                         + (size_t)bid * 32768 + t;
        const int ebase = bid * 32768;
#pragma unroll 1
        for (int it = 0; it < 32; it++) {
            float4 r[4];
#pragma unroll
            for (int q = 0; q < 4; q++)
                r[q] = __ldcs(p4 + (size_t)(it * 4 + q) * 256);
#pragma unroll
            for (int q = 0; q < 4; q++) {
                if (r[q].x != 0.0f || r[q].y != 0.0f ||
                    r[q].z != 0.0f || r[q].w != 0.0f) {    // rare: one-hot
                    int e = (ebase + (it * 4 + q) * 256 + t) << 2;
                    int k = e >> 12;           // P row
                    int j = e & (HN - 1);      // P column
                    if (r[q].x != 0.0f) d_fwdp[k] = perm_enc(j + 0);
                    if (r[q].y != 0.0f) d_fwdp[k] = perm_enc(j + 1);
                    if (r[q].z != 0.0f) d_fwdp[k] = perm_enc(j + 2);
                    if (r[q].w != 0.0f) d_fwdp[k] = perm_enc(j + 3);
                }
            }
        }
        __syncthreads();                       // block's stores done
        if (t == 0) {
            __threadfence();                   // cumulative release to L2
            atomicAdd(&d_done, 1);
        }
    }

    // ================= issue first-row loads (independent of idx) ==========
    const size_t row0 = (size_t)bid * RPB;
    float v[16];
    {
        const float4* in4 = reinterpret_cast<const float4*>(value + row0 * HN) + t * 4;
#pragma unroll
        for (int q = 0; q < 4; q++) {
            float4 x = __ldcs(in4 + q);
            v[q * 4 + 0] = x.x; v[q * 4 + 1] = x.y;
            v[q * 4 + 2] = x.z; v[q * 4 + 3] = x.w;
        }
    }

    // ================= wait for extraction (instant on replays) ============
    if (t == 0) {
        while (*(volatile int*)&d_done < NEXTRACT) __nanosleep(64);
        __threadfence();                       // acquire
    }
    __syncthreads();

    // scatter addresses for this thread's 16 source elements (both rows)
    int idx[16];
    {
        const int4* fp = reinterpret_cast<const int4*>(d_fwdp) + t * 4;
#pragma unroll
        for (int q = 0; q < 4; q++) {
            int4 w = __ldcg(fp + q);           // written this launch: L2-coherent
            idx[q * 4 + 0] = w.x; idx[q * 4 + 1] = w.y;
            idx[q * 4 + 2] = w.z; idx[q * 4 + 3] = w.w;
        }
    }

    // ================= two rows =================
#pragma unroll
    for (int r = 0; r < RPB; r++) {
        // scatter original row into permuted layout (random banks, unavoidable)
#pragma unroll
        for (int q = 0; q < 16; q++) sp[idx[q]] = v[q];

        // pass 1 (c-bits): fwht contiguous 16, store state A: addr=t*17+c (CF)
        fwht16(v);
#pragma unroll
        for (int c = 0; c < 16; c++) wk[t * WST + c] = v[c];

        // prefetch next row while smem passes run
        float vn[16];
        if (r + 1 < RPB) {
            const float4* in4 =
                reinterpret_cast<const float4*>(value + (row0 + r + 1) * HN) + t * 4;
#pragma unroll
            for (int q = 0; q < 4; q++) {
                float4 x = __ldcs(in4 + q);
                vn[q * 4 + 0] = x.x; vn[q * 4 + 1] = x.y;
                vn[q * 4 + 2] = x.z; vn[q * 4 + 3] = x.w;
            }
        }
        __syncthreads();

        // pass 2 (b-bits): read A (CF), fwht, write state B: (b*16+c)*17+a (CF)
        {
            const int a = t >> 4, c = t & 15;
            float u[16];
#pragma unroll
            for (int b = 0; b < 16; b++) u[b] = wk[(a * 16 + b) * WST + c];
            __syncthreads();          // all reads of A before B overwrites
            fwht16(u);
#pragma unroll
            for (int b = 0; b < 16; b++) wk[(b * 16 + c) * WST + a] = u[b];
        }
        __syncthreads();

        // pass 3 (a-bits) + epilogue
        {
            const int b = t >> 4, c = t & 15;
            float u[16];
#pragma unroll
            for (int a = 0; a < 16; a++) u[a] = wk[(b * 16 + c) * WST + a];
            fwht16(u);
            // epilogue: out[j] = fwht[j]/64 + orig[inv[j]], j = a*256+b*16+c
            // sp read banks (17c+16b+a) mod 32: full partition per instr -> CF
            const float* spp  = sp + c * PST + b * 16;
            float*       orow = out + (row0 + r) * HN + b * 16 + c;
#pragma unroll
            for (int a = 0; a < 16; a++)
                __stcs(orow + a * 256, u[a] * 0.015625f + spp[a]);
        }

        if (r + 1 < RPB) {
            __syncthreads();          // sp reads / wk reads done before reuse
#pragma unroll
            for (int q = 0; q < 16; q++) v[q] = vn[q];
        }
    }
}

// ---------------------------------------------------------------------------
// Inputs (metadata order): value [ROWS*N], weight [N*N] (exact H/64, unused),
// permutation [N*N].
// ---------------------------------------------------------------------------
extern "C" void kernel_launch(void* const* d_in, const int* in_sizes, int n_in,
                              void* d_out, int out_size) {
    const float* value = (const float*)d_in[0];
    const float* P     = (const float*)d_in[2];
    float* out         = (float*)d_out;
    (void)in_sizes; (void)n_in; (void)out_size;

    fused_fwht_kernel<<<HROWS / RPB, 256>>>(value, P, out);
}